// round 15
// baseline (speedup 1.0000x reference)
#include <cuda_runtime.h>
#include <cstdint>
#include <math_constants.h>

#define NN   10000
#define E0   320000
#define ET   330000
#define HIDD 256

// ---------------- scratch (device globals) ----------------------------------
__device__ __align__(256) float g_xl[NN * HIDD];
__device__ __align__(256) float g_xr[NN * HIDD];
__device__ __align__(256) float g_xl2[NN * HIDD];   // layer-2 ping-pong (split-K dst)
__device__ __align__(256) float g_xr2[NN * HIDD];
__device__ __align__(256) float g_h[NN * HIDD];     // also holds rounded-x for GEMM1
__device__ __align__(256) float g_hres[NN * HIDD];
__device__ __align__(256) float g_w1l[128 * 256];
__device__ __align__(256) float g_w1r[128 * 256];
__device__ __align__(256) float g_w2l[256 * 256];
__device__ __align__(256) float g_w2r[256 * 256];
__device__ __align__(256) int   g_src[ET];
__device__ __align__(256) int   g_dst[ET];
__device__ __align__(256) int   g_csr_src[ET];
__device__ __align__(256) int   g_rowptr[NN + 1];
__device__ __align__(256) int   g_cursor[NN];
__device__ __align__(256) int   g_deg[NN];   // zero-init at load; re-zeroed by k_scan

// ---------------- TF32 helpers ------------------------------------------------
__device__ __forceinline__ uint32_t f2tf32(float x) {
    uint32_t r;
    asm("cvt.rna.tf32.f32 %0, %1;" : "=r"(r) : "f"(x));
    return r;
}
__device__ __forceinline__ float rna(float x) { return __uint_as_float(f2tf32(x)); }

// ---------------- RNA pre-round: 5 segments in one launch --------------------
__global__ void k_round5(const float* __restrict__ s0, float* __restrict__ d0, int n0,
                         const float* __restrict__ s1, float* __restrict__ d1, int n1,
                         const float* __restrict__ s2, float* __restrict__ d2, int n2,
                         const float* __restrict__ s3, float* __restrict__ d3, int n3,
                         const float* __restrict__ s4, float* __restrict__ d4, int n4) {
    const float* s; float* d; int n;
    switch (blockIdx.y) {
        case 0: s = s0; d = d0; n = n0; break;
        case 1: s = s1; d = d1; n = n1; break;
        case 2: s = s2; d = d2; n = n2; break;
        case 3: s = s3; d = d3; n = n3; break;
        default: s = s4; d = d4; n = n4; break;
    }
    int i = (blockIdx.x * blockDim.x + threadIdx.x) * 4;
    if (i >= n) return;
    float4 v = *(const float4*)(s + i);
    v.x = rna(v.x); v.y = rna(v.y); v.z = rna(v.z); v.w = rna(v.w);
    *(float4*)(d + i) = v;
}

// ---------------- zero two buffers (split-K accumulators) --------------------
__global__ void k_zero2(float* __restrict__ a, float* __restrict__ b, int n) {
    int i = (blockIdx.x * blockDim.x + threadIdx.x) * 4;
    if (i >= n) return;
    float4 z = make_float4(0.f, 0.f, 0.f, 0.f);
    if (blockIdx.y == 0) *(float4*)(a + i) = z;
    else                 *(float4*)(b + i) = z;
}

// ---------------- CSR build --------------------------------------------------
__global__ void k_edges(const void* __restrict__ ei_raw,
                        int* __restrict__ src, int* __restrict__ dst,
                        int* __restrict__ deg) {
    __shared__ int s_is64;
    if (threadIdx.x == 0) {
        const long long* e64 = (const long long*)ei_raw;
        int v64 = 1;
#pragma unroll
        for (int j = 0; j < 16; j++) {
            long long v = e64[j];
            if (v < 0 || v >= NN) { v64 = 0; break; }
        }
        s_is64 = v64;
    }
    __syncthreads();

    int t = blockIdx.x * blockDim.x + threadIdx.x;
    int e = t * 4;
    if (e >= ET) return;

    int s[4], d[4];
    if (e < E0) {
        if (s_is64) {
            const longlong2* p = (const longlong2*)ei_raw;
            longlong2 s01 = p[e / 2], s23 = p[e / 2 + 1];
            longlong2 d01 = p[(E0 + e) / 2], d23 = p[(E0 + e) / 2 + 1];
            s[0] = (int)s01.x; s[1] = (int)s01.y; s[2] = (int)s23.x; s[3] = (int)s23.y;
            d[0] = (int)d01.x; d[1] = (int)d01.y; d[2] = (int)d23.x; d[3] = (int)d23.y;
        } else {
            const int4* p = (const int4*)ei_raw;
            int4 sv = p[e / 4];
            int4 dv = p[(E0 + e) / 4];
            s[0] = sv.x; s[1] = sv.y; s[2] = sv.z; s[3] = sv.w;
            d[0] = dv.x; d[1] = dv.y; d[2] = dv.z; d[3] = dv.w;
        }
    } else {
#pragma unroll
        for (int j = 0; j < 4; j++) { s[j] = e - E0 + j; d[j] = s[j]; }
    }
#pragma unroll
    for (int j = 0; j < 4; j++) {
        s[j] = min(max(s[j], 0), NN - 1);
        d[j] = min(max(d[j], 0), NN - 1);
    }
    *(int4*)(src + e) = make_int4(s[0], s[1], s[2], s[3]);
    *(int4*)(dst + e) = make_int4(d[0], d[1], d[2], d[3]);
#pragma unroll
    for (int j = 0; j < 4; j++) atomicAdd(deg + d[j], 1);
}

#define NPAD 10240
__global__ void __launch_bounds__(1024)
k_scan(int* __restrict__ deg, int* __restrict__ row_ptr,
       int* __restrict__ cursor) {
    __shared__ int sdeg[NPAD];
    __shared__ int wsum[32];
    const int CH = NPAD / 1024;  // 10
    int t = threadIdx.x;
    int lane = t & 31, warp = t >> 5;

    for (int i = t; i < NPAD; i += 1024) sdeg[i] = (i < NN) ? deg[i] : 0;
    __syncthreads();
    for (int i = t; i < NN; i += 1024) deg[i] = 0;

    int base = t * CH;
    int local[CH];
    int s = 0;
#pragma unroll
    for (int i = 0; i < CH; i++) {
        int v = sdeg[base + i];
        local[i] = s;
        s += v;
    }
    int chunk = s;
#pragma unroll
    for (int off = 1; off < 32; off <<= 1) {
        int v = __shfl_up_sync(0xffffffffu, s, off);
        if (lane >= off) s += v;
    }
    if (lane == 31) wsum[warp] = s;
    __syncthreads();
    if (warp == 0) {
        int w = wsum[lane];
#pragma unroll
        for (int off = 1; off < 32; off <<= 1) {
            int v = __shfl_up_sync(0xffffffffu, w, off);
            if (lane >= off) w += v;
        }
        wsum[lane] = w;
    }
    __syncthreads();
    int woff = (warp > 0) ? wsum[warp - 1] : 0;
    int excl = woff + s - chunk;
#pragma unroll
    for (int i = 0; i < CH; i++) sdeg[base + i] = excl + local[i];
    __syncthreads();

    for (int i = t; i < NN; i += 1024) {
        int p = sdeg[i];
        row_ptr[i] = p;
        cursor[i]  = p;
    }
    if (t == 1023) row_ptr[NN] = woff + s;
}

__global__ void k_scatter(const int* __restrict__ src, const int* __restrict__ dst,
                          int* __restrict__ cursor, int* __restrict__ csr_src) {
    int t = blockIdx.x * blockDim.x + threadIdx.x;
    int e = t * 4;
    if (e >= ET) return;
    int4 sv = *(const int4*)(src + e);
    int4 dv = *(const int4*)(dst + e);
    int ss[4] = {sv.x, sv.y, sv.z, sv.w};
    int dd[4] = {dv.x, dv.y, dv.z, dv.w};
#pragma unroll
    for (int j = 0; j < 4; j++) {
        int pos = atomicAdd(cursor + dd[j], 1);
        csr_src[pos] = ss[j];
    }
}

// ---------------- TF32 MMA / cp.async ----------------------------------------
__device__ __forceinline__ void mma_tf32(float* c, const uint32_t* a, const uint32_t* b) {
    asm volatile(
        "mma.sync.aligned.m16n8k8.row.col.f32.tf32.tf32.f32 "
        "{%0,%1,%2,%3}, {%4,%5,%6,%7}, {%8,%9}, {%0,%1,%2,%3};"
        : "+f"(c[0]), "+f"(c[1]), "+f"(c[2]), "+f"(c[3])
        : "r"(a[0]), "r"(a[1]), "r"(a[2]), "r"(a[3]), "r"(b[0]), "r"(b[1]));
}

__device__ __forceinline__ void cp16(uint32_t dst, const void* src, bool pred) {
    int sz = pred ? 16 : 0;
    asm volatile("cp.async.ca.shared.global [%0], [%1], 16, %2;"
                 :: "r"(dst), "l"(src), "r"(sz) : "memory");
}
__device__ __forceinline__ void cp_commit() {
    asm volatile("cp.async.commit_group;" ::: "memory");
}
template <int N>
__device__ __forceinline__ void cp_wait() {
    asm volatile("cp.async.wait_group %0;" :: "n"(N) : "memory");
}
__device__ __forceinline__ void red2(float* p, float x, float y) {
    asm volatile("red.global.add.v2.f32 [%0], {%1,%2};"
                 :: "l"(p), "f"(x), "f"(y) : "memory");
}

// ---------------- dual TF32 GEMM 128x64, cp.async 3-stage, optional split-K -
// Inputs pre-rounded. KSPLIT=1: plain store. KSPLIT=2: red-add (C pre-zeroed).
// grid.z = 2*KSPLIT: (z & 1) selects B/C pair, (z >> 1) selects K-half.
#define STAGES 3
#define PA_ROW 20
#define PB_ROW 72
#define A_TILE (128 * PA_ROW)
#define B_TILE (16 * PB_ROW)
template <int KSPLIT>
__global__ void __launch_bounds__(256, 3)
k_gemm_tf32_dual(const float* __restrict__ A,
                 const float* __restrict__ B0, const float* __restrict__ B1,
                 float* __restrict__ C0, float* __restrict__ C1,
                 int M, int N, int Ktot) {
    int zz = blockIdx.z;
    const float* B = (zz & 1) ? B1 : B0;
    float*       C = (zz & 1) ? C1 : C0;
    const int Kloop = Ktot / KSPLIT;
    const int kh = zz >> 1;
    const float* Ab = A + (size_t)kh * Kloop;          // row stride Ktot
    const float* Bb = B + (size_t)kh * Kloop * N;      // row stride N

    __shared__ float As[STAGES][A_TILE];
    __shared__ float Bs[STAGES][B_TILE];

    int tid  = threadIdx.x;
    int warp = tid >> 5, lane = tid & 31;
    int gid = lane >> 2, tig = lane & 3;
    int m_base = (warp & 3) * 32;
    int n_base = (warp >> 2) * 32;
    int m0 = blockIdx.y * 128, n0 = blockIdx.x * 64;

    uint32_t as_base = (uint32_t)__cvta_generic_to_shared(&As[0][0]);
    uint32_t bs_base = (uint32_t)__cvta_generic_to_shared(&Bs[0][0]);

    float acc[2][4][4];
#pragma unroll
    for (int im = 0; im < 2; im++)
#pragma unroll
        for (int in = 0; in < 4; in++)
#pragma unroll
            for (int r = 0; r < 4; r++) acc[im][in][r] = 0.0f;

    auto load_tile = [&](int k0, int st) {
#pragma unroll
        for (int l = 0; l < 2; l++) {
            int c = tid + l * 256;
            int row = c >> 2, sub = c & 3;
            int gm = m0 + row;
            const float* srcp = Ab + (size_t)gm * Ktot + k0 + sub * 4;
            uint32_t dst = as_base + (st * A_TILE + row * PA_ROW + sub * 4) * 4;
            cp16(dst, srcp, gm < M);
        }
        {
            int row = tid >> 4, sub = tid & 15;
            const float* srcp = Bb + (size_t)(k0 + row) * N + n0 + sub * 4;
            uint32_t dst = bs_base + (st * B_TILE + row * PB_ROW + sub * 4) * 4;
            cp16(dst, srcp, true);
        }
    };

    int nk = Kloop >> 4;
#pragma unroll
    for (int p = 0; p < STAGES - 1; p++) {
        if (p < nk) load_tile(p * 16, p);
        cp_commit();
    }

    for (int t = 0; t < nk; t++) {
        cp_wait<STAGES - 2>();
        __syncthreads();
        int nt = t + STAGES - 1;
        if (nt < nk) load_tile(nt * 16, nt % STAGES);
        cp_commit();

        int st = t % STAGES;
        const float* Ast = As[st];
        const float* Bst = Bs[st];
#pragma unroll
        for (int ks = 0; ks < 2; ks++) {
            int k0 = ks * 8;
            uint32_t af[2][4], bf[4][2];
#pragma unroll
            for (int im = 0; im < 2; im++) {
                int mrow = m_base + im * 16 + gid;
                af[im][0] = __float_as_uint(Ast[mrow * PA_ROW + k0 + tig]);
                af[im][1] = __float_as_uint(Ast[(mrow + 8) * PA_ROW + k0 + tig]);
                af[im][2] = __float_as_uint(Ast[mrow * PA_ROW + k0 + tig + 4]);
                af[im][3] = __float_as_uint(Ast[(mrow + 8) * PA_ROW + k0 + tig + 4]);
            }
#pragma unroll
            for (int in = 0; in < 4; in++) {
                int ncol = n_base + in * 8 + gid;
                bf[in][0] = __float_as_uint(Bst[(k0 + tig) * PB_ROW + ncol]);
                bf[in][1] = __float_as_uint(Bst[(k0 + tig + 4) * PB_ROW + ncol]);
            }
#pragma unroll
            for (int im = 0; im < 2; im++)
#pragma unroll
                for (int in = 0; in < 4; in++)
                    mma_tf32(acc[im][in], af[im], bf[in]);
        }
        __syncthreads();
    }

#pragma unroll
    for (int im = 0; im < 2; im++) {
#pragma unroll
        for (int in = 0; in < 4; in++) {
            int row = m0 + m_base + im * 16 + gid;
            int col = n0 + n_base + in * 8 + 2 * tig;
            if (KSPLIT == 1) {
                if (row < M)
                    *(float2*)(C + (size_t)row * N + col) = make_float2(acc[im][in][0], acc[im][in][1]);
                if (row + 8 < M)
                    *(float2*)(C + (size_t)(row + 8) * N + col) = make_float2(acc[im][in][2], acc[im][in][3]);
            } else {
                if (row < M)
                    red2(C + (size_t)row * N + col, acc[im][in][0], acc[im][in][1]);
                if (row + 8 < M)
                    red2(C + (size_t)(row + 8) * N + col, acc[im][in][2], acc[im][in][3]);
            }
        }
    }
}

// ---------------- dual SGEMM 64x64 FFMA (layer-3, N=32 each) ----------------
__global__ void __launch_bounds__(256, 4)
k_gemm_dual(const float* __restrict__ A,
            const float* __restrict__ B0, const float* __restrict__ B1,
            float* __restrict__ C0, float* __restrict__ C1,
            int M, int N, int K) {
    const float* B = blockIdx.z ? B1 : B0;
    float*       C = blockIdx.z ? C1 : C0;

    __shared__ __align__(16) float As[16][64];
    __shared__ __align__(16) float Bs[16][64];
    int tid = threadIdx.x;
    int tx = tid & 15, ty = tid >> 4;
    int m0 = blockIdx.y * 64, n0 = blockIdx.x * 64;

    float acc[4][4];
#pragma unroll
    for (int i = 0; i < 4; i++)
#pragma unroll
        for (int j = 0; j < 4; j++) acc[i][j] = 0.0f;

    for (int k0 = 0; k0 < K; k0 += 16) {
        {
            int r = tid >> 2;
            int kq = (tid & 3) * 4;
            int gm = m0 + r;
            float4 v = make_float4(0.f, 0.f, 0.f, 0.f);
            if (gm < M) v = *(const float4*)(A + (size_t)gm * K + k0 + kq);
            As[kq + 0][r] = v.x;
            As[kq + 1][r] = v.y;
            As[kq + 2][r] = v.z;
            As[kq + 3][r] = v.w;
        }
        {
            int r = tid >> 4;
            int cq = (tid & 15) * 4;
            int gn = n0 + cq;
            float4 v = make_float4(0.f, 0.f, 0.f, 0.f);
            if (gn + 3 < N) v = *(const float4*)(B + (size_t)(k0 + r) * N + gn);
            *(float4*)&Bs[r][cq] = v;
        }
        __syncthreads();
#pragma unroll
        for (int k = 0; k < 16; k++) {
            float4 a = *(const float4*)&As[k][ty * 4];
            float4 b = *(const float4*)&Bs[k][tx * 4];
            float ar[4] = {a.x, a.y, a.z, a.w};
            float br[4] = {b.x, b.y, b.z, b.w};
#pragma unroll
            for (int i = 0; i < 4; i++)
#pragma unroll
                for (int j = 0; j < 4; j++) acc[i][j] += ar[i] * br[j];
        }
        __syncthreads();
    }
#pragma unroll
    for (int i = 0; i < 4; i++) {
        int gm = m0 + ty * 4 + i;
        if (gm >= M) continue;
#pragma unroll
        for (int j = 0; j < 4; j++) {
            int gn = n0 + tx * 4 + j;
            if (gn < N) C[(size_t)gm * N + gn] = acc[i][j];
        }
    }
}

// ---------------- fused GAT edge phase: warp/node, quad online softmax ------
template <int H, int MODE>
__global__ void __launch_bounds__(256)
k_gat(const float* __restrict__ xl, const float* __restrict__ xr,
      const float* __restrict__ att, const float* __restrict__ bias,
      const int* __restrict__ row_ptr, const int* __restrict__ csr_src,
      const float* __restrict__ hres_in,
      float* __restrict__ out, float* __restrict__ hres_out) {
    constexpr int D = H * 32;
    constexpr int R = D / 32;
    constexpr int L = 32 / H;

    int node = (int)((blockIdx.x * (unsigned)blockDim.x + threadIdx.x) >> 5);
    int lane = threadIdx.x & 31;
    if (node >= NN) return;

    float xrv[R], attv[R], acc[R];
    {
        const float* xrp = xr + (size_t)node * D + lane * R;
#pragma unroll
        for (int q = 0; q < R / 4; q++) *(float4*)&xrv[q * 4] = *(const float4*)(xrp + q * 4);
#pragma unroll
        for (int j = (R / 4) * 4; j < R; j++) xrv[j] = xrp[j];
#pragma unroll
        for (int j = 0; j < R; j++) { attv[j] = att[lane * R + j]; acc[j] = 0.0f; }
    }
    float m = -CUDART_INF_F, denom = 0.0f;

    auto load_x = [&](int s, float* dstf) {
        const float* xp = xl + (size_t)s * D + lane * R;
#pragma unroll
        for (int q = 0; q < R / 4; q++) *(float4*)&dstf[q * 4] = *(const float4*)(xp + q * 4);
#pragma unroll
        for (int j = (R / 4) * 4; j < R; j++) dstf[j] = xp[j];
    };
    auto score = [&](const float* c) {
        float p = 0.0f;
#pragma unroll
        for (int j = 0; j < R; j++) {
            float v = c[j] + xrv[j];
            v = v > 0.0f ? v : 0.2f * v;
            p = fmaf(v, attv[j], p);
        }
        return p;
    };

    int e   = row_ptr[node];
    int end = row_ptr[node + 1];

    for (; e + 4 <= end; e += 4) {
        int s0 = csr_src[e], s1 = csr_src[e + 1], s2 = csr_src[e + 2], s3 = csr_src[e + 3];
        float c0[R], c1[R], c2[R], c3[R];
        load_x(s0, c0); load_x(s1, c1); load_x(s2, c2); load_x(s3, c3);

        float p0 = score(c0), p1 = score(c1), p2 = score(c2), p3 = score(c3);
#pragma unroll
        for (int o = 1; o < L; o <<= 1) {
            p0 += __shfl_xor_sync(0xffffffffu, p0, o);
            p1 += __shfl_xor_sync(0xffffffffu, p1, o);
            p2 += __shfl_xor_sync(0xffffffffu, p2, o);
            p3 += __shfl_xor_sync(0xffffffffu, p3, o);
        }

        float mq = fmaxf(fmaxf(p0, p1), fmaxf(p2, p3));
        float w0 = __expf(p0 - mq), w1 = __expf(p1 - mq);
        float w2 = __expf(p2 - mq), w3 = __expf(p3 - mq);
        float nm = fmaxf(m, mq);
        float so = __expf(m - nm);
        float sn = __expf(mq - nm);
        denom = denom * so + (w0 + w1 + w2 + w3) * sn;
        float w0n = w0 * sn, w1n = w1 * sn, w2n = w2 * sn, w3n = w3 * sn;
#pragma unroll
        for (int j = 0; j < R; j++) {
            float t = fmaf(w1n, c1[j], w0n * c0[j]);
            t = fmaf(w2n, c2[j], t);
            t = fmaf(w3n, c3[j], t);
            acc[j] = fmaf(acc[j], so, t);
        }
        m = nm;
    }
    for (; e + 2 <= end; e += 2) {
        int s0 = csr_src[e], s1 = csr_src[e + 1];
        float c0[R], c1[R];
        load_x(s0, c0); load_x(s1, c1);
        float p0 = score(c0), p1 = score(c1);
#pragma unroll
        for (int o = 1; o < L; o <<= 1) {
            p0 += __shfl_xor_sync(0xffffffffu, p0, o);
            p1 += __shfl_xor_sync(0xffffffffu, p1, o);
        }
        float mq = fmaxf(p0, p1);
        float w0 = __expf(p0 - mq), w1 = __expf(p1 - mq);
        float nm = fmaxf(m, mq);
        float so = __expf(m - nm);
        float sn = __expf(mq - nm);
        denom = denom * so + (w0 + w1) * sn;
        float w0n = w0 * sn, w1n = w1 * sn;
#pragma unroll
        for (int j = 0; j < R; j++) {
            float t = fmaf(w1n, c1[j], w0n * c0[j]);
            acc[j] = fmaf(acc[j], so, t);
        }
        m = nm;
    }
    if (e < end) {
        int s0 = csr_src[e];
        float c0[R];
        load_x(s0, c0);
        float p0 = score(c0);
#pragma unroll
        for (int o = 1; o < L; o <<= 1) p0 += __shfl_xor_sync(0xffffffffu, p0, o);
        float nm = fmaxf(m, p0);
        float so = __expf(m - nm);
        float w  = __expf(p0 - nm);
        denom = denom * so + w;
#pragma unroll
        for (int j = 0; j < R; j++) acc[j] = fmaf(acc[j], so, w * c0[j]);
        m = nm;
    }

    float inv = 1.0f / (denom + 1e-16f);
    float* op = out + (size_t)node * D + lane * R;
    float res[R];
#pragma unroll
    for (int j = 0; j < R; j++) {
        float v = acc[j] * inv + bias[lane * R + j];
        if (MODE == 0) v = v > 0.0f ? v : 0.0f;
        if (MODE == 1) v += hres_in[(size_t)node * D + lane * R + j];
        res[j] = v;
    }
    if (MODE == 0) {
        float* hp = hres_out + (size_t)node * D + lane * R;
        float rr[R];
#pragma unroll
        for (int j = 0; j < R; j++) rr[j] = rna(res[j]);
#pragma unroll
        for (int q = 0; q < R / 4; q++) {
            *(float4*)(hp + q * 4) = *(float4*)&res[q * 4];
            *(float4*)(op + q * 4) = *(float4*)&rr[q * 4];
        }
#pragma unroll
        for (int j = (R / 4) * 4; j < R; j++) { hp[j] = res[j]; op[j] = rr[j]; }
    } else {
#pragma unroll
        for (int q = 0; q < R / 4; q++) *(float4*)(op + q * 4) = *(float4*)&res[q * 4];
#pragma unroll
        for (int j = (R / 4) * 4; j < R; j++) op[j] = res[j];
    }
}

// ---------------- stream/event resources (host-side only) -------------------
struct SideStream {
    cudaStream_t s2;
    cudaEvent_t evFork, evJ1, evFork2, evJ2;
    SideStream() {
        cudaStreamCreateWithFlags(&s2, cudaStreamNonBlocking);
        cudaEventCreateWithFlags(&evFork, cudaEventDisableTiming);
        cudaEventCreateWithFlags(&evJ1, cudaEventDisableTiming);
        cudaEventCreateWithFlags(&evFork2, cudaEventDisableTiming);
        cudaEventCreateWithFlags(&evJ2, cudaEventDisableTiming);
    }
};

// ---------------- launch ----------------------------------------------------
extern "C" void kernel_launch(void* const* d_in, const int* in_sizes, int n_in,
                              void* d_out, int out_size) {
    const float* x   = (const float*)d_in[0];
    const float* W1l = (const float*)d_in[1];
    const float* W1r = (const float*)d_in[2];
    const float* a1  = (const float*)d_in[3];
    const float* b1  = (const float*)d_in[4];
    const float* W2l = (const float*)d_in[5];
    const float* W2r = (const float*)d_in[6];
    const float* a2  = (const float*)d_in[7];
    const float* b2  = (const float*)d_in[8];
    const float* W3l = (const float*)d_in[9];
    const float* W3r = (const float*)d_in[10];
    const float* a3  = (const float*)d_in[11];
    const float* b3  = (const float*)d_in[12];
    const void*  ei  = (const void*)d_in[13];
    float* out = (float*)d_out;

    float *xl, *xr, *xl2, *xr2, *hh, *hres, *w1l, *w1r, *w2l, *w2r;
    int *src, *dst, *csr, *rowp, *cur, *deg;
    cudaGetSymbolAddress((void**)&xl, g_xl);
    cudaGetSymbolAddress((void**)&xr, g_xr);
    cudaGetSymbolAddress((void**)&xl2, g_xl2);
    cudaGetSymbolAddress((void**)&xr2, g_xr2);
    cudaGetSymbolAddress((void**)&hh, g_h);
    cudaGetSymbolAddress((void**)&hres, g_hres);
    cudaGetSymbolAddress((void**)&w1l, g_w1l);
    cudaGetSymbolAddress((void**)&w1r, g_w1r);
    cudaGetSymbolAddress((void**)&w2l, g_w2l);
    cudaGetSymbolAddress((void**)&w2r, g_w2r);
    cudaGetSymbolAddress((void**)&src, g_src);
    cudaGetSymbolAddress((void**)&dst, g_dst);
    cudaGetSymbolAddress((void**)&csr, g_csr_src);
    cudaGetSymbolAddress((void**)&rowp, g_rowptr);
    cudaGetSymbolAddress((void**)&cur, g_cursor);
    cudaGetSymbolAddress((void**)&deg, g_deg);

    static SideStream S;

    const int TB = 256;
    int eb4 = (ET / 4 + TB - 1) / TB;
    int nwb = (NN * 32 + TB - 1) / TB;

    dim3 gBig((256 + 63) / 64, (NN + 127) / 128, 2);    // GEMM1: z = 2
    dim3 gBig2((256 + 63) / 64, (NN + 127) / 128, 4);   // GEMM2 split-K: z = 4
    dim3 gSm(1, (NN + 63) / 64, 2);
    dim3 gRound((NN * 128 / 4 + TB - 1) / TB, 5);
    dim3 gZero((NN * HIDD / 4 + TB - 1) / TB, 2);

    // fork the side stream INTO the capture (event on stream 0 first).
    cudaEventRecord(S.evFork, 0);
    cudaStreamWaitEvent(S.s2, S.evFork, 0);

    // main: CSR chain. side: round + GEMM1 (4th submission = ncu control slot).
    k_edges<<<eb4, TB>>>(ei, src, dst, deg);                                       // 1
    k_scan<<<1, 1024>>>(deg, rowp, cur);                                           // 2
    k_round5<<<gRound, TB, 0, S.s2>>>(x, hh, NN * 128,                             // 3
                                      W1l, w1l, 128 * 256,
                                      W1r, w1r, 128 * 256,
                                      W2l, w2l, 256 * 256,
                                      W2r, w2r, 256 * 256);
    k_gemm_tf32_dual<1><<<gBig, TB, 0, S.s2>>>(hh, w1l, w1r, xl, xr, NN, 256, 128); // 4
    k_scatter<<<eb4, TB>>>(src, dst, cur, csr);                                    // 5
    cudaEventRecord(S.evJ1, S.s2);
    cudaStreamWaitEvent(0, S.evJ1, 0);

    // ---------- layer 1 (Fin=128, H=8) ----------
    // re-fork side stream for zero2 (overlaps gat1)
    cudaEventRecord(S.evFork2, 0);
    cudaStreamWaitEvent(S.s2, S.evFork2, 0);
    k_gat<8, 0><<<nwb, TB>>>(xl, xr, a1, b1, rowp, csr, nullptr, hh, hres);
    k_zero2<<<gZero, TB, 0, S.s2>>>(xl2, xr2, NN * HIDD);
    cudaEventRecord(S.evJ2, S.s2);
    cudaStreamWaitEvent(0, S.evJ2, 0);

    // ---------- layer 2 (Fin=256, H=8, residual); split-K=2 GEMM -------------
    k_gemm_tf32_dual<2><<<gBig2, TB>>>(hh, w2l, w2r, xl2, xr2, NN, 256, 256);
    k_gat<8, 1><<<nwb, TB>>>(xl2, xr2, a2, b2, rowp, csr, hres, hh, nullptr);

    // ---------- layer 3 (Fin=256, H=1, FFMA fp32) ----------
    k_gemm_dual<<<gSm, TB>>>(hh, W3l, W3r, xl, xr, NN, 32, 256);
    k_gat<1, 2><<<nwb, TB>>>(xl, xr, a3, b3, rowp, csr, nullptr, out, nullptr);
}

// round 16
// speedup vs baseline: 1.0435x; 1.0435x over previous
#include <cuda_runtime.h>
#include <cstdint>
#include <math_constants.h>

#define NN   10000
#define E0   320000
#define ET   330000
#define HIDD 256

// ---------------- scratch (device globals) ----------------------------------
__device__ __align__(256) float g_xl[NN * HIDD];
__device__ __align__(256) float g_xr[NN * HIDD];
__device__ __align__(256) float g_h[NN * HIDD];     // also holds rounded-x for GEMM1
__device__ __align__(256) float g_hres[NN * HIDD];
__device__ __align__(256) float g_w1l[128 * 256];
__device__ __align__(256) float g_w1r[128 * 256];
__device__ __align__(256) float g_w2l[256 * 256];
__device__ __align__(256) float g_w2r[256 * 256];
__device__ __align__(256) int   g_src[ET];
__device__ __align__(256) int   g_dst[ET];
__device__ __align__(256) int   g_csr_src[ET];
__device__ __align__(256) int   g_rowptr[NN + 1];
__device__ __align__(256) int   g_cursor[NN];
__device__ __align__(256) int   g_deg[NN];   // zero-init at load; re-zeroed by k_scan

// ---------------- TF32 helpers ------------------------------------------------
__device__ __forceinline__ uint32_t f2tf32(float x) {
    uint32_t r;
    asm("cvt.rna.tf32.f32 %0, %1;" : "=r"(r) : "f"(x));
    return r;
}
__device__ __forceinline__ float rna(float x) { return __uint_as_float(f2tf32(x)); }

// ---------------- RNA pre-round: 5 segments in one launch --------------------
__global__ void k_round5(const float* __restrict__ s0, float* __restrict__ d0, int n0,
                         const float* __restrict__ s1, float* __restrict__ d1, int n1,
                         const float* __restrict__ s2, float* __restrict__ d2, int n2,
                         const float* __restrict__ s3, float* __restrict__ d3, int n3,
                         const float* __restrict__ s4, float* __restrict__ d4, int n4) {
    const float* s; float* d; int n;
    switch (blockIdx.y) {
        case 0: s = s0; d = d0; n = n0; break;
        case 1: s = s1; d = d1; n = n1; break;
        case 2: s = s2; d = d2; n = n2; break;
        case 3: s = s3; d = d3; n = n3; break;
        default: s = s4; d = d4; n = n4; break;
    }
    int i = (blockIdx.x * blockDim.x + threadIdx.x) * 4;
    if (i >= n) return;
    float4 v = *(const float4*)(s + i);
    v.x = rna(v.x); v.y = rna(v.y); v.z = rna(v.z); v.w = rna(v.w);
    *(float4*)(d + i) = v;
}

// ---------------- CSR build --------------------------------------------------
__global__ void k_edges(const void* __restrict__ ei_raw,
                        int* __restrict__ src, int* __restrict__ dst,
                        int* __restrict__ deg) {
    __shared__ int s_is64;
    if (threadIdx.x == 0) {
        const long long* e64 = (const long long*)ei_raw;
        int v64 = 1;
#pragma unroll
        for (int j = 0; j < 16; j++) {
            long long v = e64[j];
            if (v < 0 || v >= NN) { v64 = 0; break; }
        }
        s_is64 = v64;
    }
    __syncthreads();

    int t = blockIdx.x * blockDim.x + threadIdx.x;
    int e = t * 4;
    if (e >= ET) return;

    int s[4], d[4];
    if (e < E0) {
        if (s_is64) {
            const longlong2* p = (const longlong2*)ei_raw;
            longlong2 s01 = p[e / 2], s23 = p[e / 2 + 1];
            longlong2 d01 = p[(E0 + e) / 2], d23 = p[(E0 + e) / 2 + 1];
            s[0] = (int)s01.x; s[1] = (int)s01.y; s[2] = (int)s23.x; s[3] = (int)s23.y;
            d[0] = (int)d01.x; d[1] = (int)d01.y; d[2] = (int)d23.x; d[3] = (int)d23.y;
        } else {
            const int4* p = (const int4*)ei_raw;
            int4 sv = p[e / 4];
            int4 dv = p[(E0 + e) / 4];
            s[0] = sv.x; s[1] = sv.y; s[2] = sv.z; s[3] = sv.w;
            d[0] = dv.x; d[1] = dv.y; d[2] = dv.z; d[3] = dv.w;
        }
    } else {
#pragma unroll
        for (int j = 0; j < 4; j++) { s[j] = e - E0 + j; d[j] = s[j]; }
    }
#pragma unroll
    for (int j = 0; j < 4; j++) {
        s[j] = min(max(s[j], 0), NN - 1);
        d[j] = min(max(d[j], 0), NN - 1);
    }
    *(int4*)(src + e) = make_int4(s[0], s[1], s[2], s[3]);
    *(int4*)(dst + e) = make_int4(d[0], d[1], d[2], d[3]);
#pragma unroll
    for (int j = 0; j < 4; j++) atomicAdd(deg + d[j], 1);
}

#define NPAD 10240
__global__ void __launch_bounds__(1024)
k_scan(int* __restrict__ deg, int* __restrict__ row_ptr,
       int* __restrict__ cursor) {
    __shared__ int sdeg[NPAD];
    __shared__ int wsum[32];
    const int CH = NPAD / 1024;  // 10
    int t = threadIdx.x;
    int lane = t & 31, warp = t >> 5;

    for (int i = t; i < NPAD; i += 1024) sdeg[i] = (i < NN) ? deg[i] : 0;
    __syncthreads();
    for (int i = t; i < NN; i += 1024) deg[i] = 0;

    int base = t * CH;
    int local[CH];
    int s = 0;
#pragma unroll
    for (int i = 0; i < CH; i++) {
        int v = sdeg[base + i];
        local[i] = s;
        s += v;
    }
    int chunk = s;
#pragma unroll
    for (int off = 1; off < 32; off <<= 1) {
        int v = __shfl_up_sync(0xffffffffu, s, off);
        if (lane >= off) s += v;
    }
    if (lane == 31) wsum[warp] = s;
    __syncthreads();
    if (warp == 0) {
        int w = wsum[lane];
#pragma unroll
        for (int off = 1; off < 32; off <<= 1) {
            int v = __shfl_up_sync(0xffffffffu, w, off);
            if (lane >= off) w += v;
        }
        wsum[lane] = w;
    }
    __syncthreads();
    int woff = (warp > 0) ? wsum[warp - 1] : 0;
    int excl = woff + s - chunk;
#pragma unroll
    for (int i = 0; i < CH; i++) sdeg[base + i] = excl + local[i];
    __syncthreads();

    for (int i = t; i < NN; i += 1024) {
        int p = sdeg[i];
        row_ptr[i] = p;
        cursor[i]  = p;
    }
    if (t == 1023) row_ptr[NN] = woff + s;
}

__global__ void k_scatter(const int* __restrict__ src, const int* __restrict__ dst,
                          int* __restrict__ cursor, int* __restrict__ csr_src) {
    int t = blockIdx.x * blockDim.x + threadIdx.x;
    int e = t * 4;
    if (e >= ET) return;
    int4 sv = *(const int4*)(src + e);
    int4 dv = *(const int4*)(dst + e);
    int ss[4] = {sv.x, sv.y, sv.z, sv.w};
    int dd[4] = {dv.x, dv.y, dv.z, dv.w};
#pragma unroll
    for (int j = 0; j < 4; j++) {
        int pos = atomicAdd(cursor + dd[j], 1);
        csr_src[pos] = ss[j];
    }
}

// ---------------- TF32 MMA / cp.async ----------------------------------------
__device__ __forceinline__ void mma_tf32(float* c, const uint32_t* a, const uint32_t* b) {
    asm volatile(
        "mma.sync.aligned.m16n8k8.row.col.f32.tf32.tf32.f32 "
        "{%0,%1,%2,%3}, {%4,%5,%6,%7}, {%8,%9}, {%0,%1,%2,%3};"
        : "+f"(c[0]), "+f"(c[1]), "+f"(c[2]), "+f"(c[3])
        : "r"(a[0]), "r"(a[1]), "r"(a[2]), "r"(a[3]), "r"(b[0]), "r"(b[1]));
}

__device__ __forceinline__ void cp16(uint32_t dst, const void* src, bool pred) {
    int sz = pred ? 16 : 0;
    asm volatile("cp.async.ca.shared.global [%0], [%1], 16, %2;"
                 :: "r"(dst), "l"(src), "r"(sz) : "memory");
}
__device__ __forceinline__ void cp_commit() {
    asm volatile("cp.async.commit_group;" ::: "memory");
}
template <int N>
__device__ __forceinline__ void cp_wait() {
    asm volatile("cp.async.wait_group %0;" :: "n"(N) : "memory");
}

// ---------------- dual TF32 GEMM 128x64, cp.async 3-stage, pre-rounded ------
#define STAGES 3
#define PA_ROW 20
#define PB_ROW 72
#define A_TILE (128 * PA_ROW)
#define B_TILE (16 * PB_ROW)
__global__ void __launch_bounds__(256, 3)
k_gemm_tf32_dual(const float* __restrict__ A,
                 const float* __restrict__ B0, const float* __restrict__ B1,
                 float* __restrict__ C0, float* __restrict__ C1,
                 int M, int N, int K) {
    const float* B = blockIdx.z ? B1 : B0;
    float*       C = blockIdx.z ? C1 : C0;

    __shared__ float As[STAGES][A_TILE];
    __shared__ float Bs[STAGES][B_TILE];

    int tid  = threadIdx.x;
    int warp = tid >> 5, lane = tid & 31;
    int gid = lane >> 2, tig = lane & 3;
    int m_base = (warp & 3) * 32;
    int n_base = (warp >> 2) * 32;
    int m0 = blockIdx.y * 128, n0 = blockIdx.x * 64;

    uint32_t as_base = (uint32_t)__cvta_generic_to_shared(&As[0][0]);
    uint32_t bs_base = (uint32_t)__cvta_generic_to_shared(&Bs[0][0]);

    float acc[2][4][4];
#pragma unroll
    for (int im = 0; im < 2; im++)
#pragma unroll
        for (int in = 0; in < 4; in++)
#pragma unroll
            for (int r = 0; r < 4; r++) acc[im][in][r] = 0.0f;

    auto load_tile = [&](int k0, int st) {
#pragma unroll
        for (int l = 0; l < 2; l++) {
            int c = tid + l * 256;
            int row = c >> 2, sub = c & 3;
            int gm = m0 + row;
            const float* srcp = A + (size_t)gm * K + k0 + sub * 4;
            uint32_t dst = as_base + (st * A_TILE + row * PA_ROW + sub * 4) * 4;
            cp16(dst, srcp, gm < M);
        }
        {
            int row = tid >> 4, sub = tid & 15;
            const float* srcp = B + (size_t)(k0 + row) * N + n0 + sub * 4;
            uint32_t dst = bs_base + (st * B_TILE + row * PB_ROW + sub * 4) * 4;
            cp16(dst, srcp, true);
        }
    };

    int nk = K >> 4;
#pragma unroll
    for (int p = 0; p < STAGES - 1; p++) {
        if (p < nk) load_tile(p * 16, p);
        cp_commit();
    }

    for (int t = 0; t < nk; t++) {
        cp_wait<STAGES - 2>();
        __syncthreads();
        int nt = t + STAGES - 1;
        if (nt < nk) load_tile(nt * 16, nt % STAGES);
        cp_commit();

        int st = t % STAGES;
        const float* Ast = As[st];
        const float* Bst = Bs[st];
#pragma unroll
        for (int ks = 0; ks < 2; ks++) {
            int k0 = ks * 8;
            uint32_t af[2][4], bf[4][2];
#pragma unroll
            for (int im = 0; im < 2; im++) {
                int mrow = m_base + im * 16 + gid;
                af[im][0] = __float_as_uint(Ast[mrow * PA_ROW + k0 + tig]);
                af[im][1] = __float_as_uint(Ast[(mrow + 8) * PA_ROW + k0 + tig]);
                af[im][2] = __float_as_uint(Ast[mrow * PA_ROW + k0 + tig + 4]);
                af[im][3] = __float_as_uint(Ast[(mrow + 8) * PA_ROW + k0 + tig + 4]);
            }
#pragma unroll
            for (int in = 0; in < 4; in++) {
                int ncol = n_base + in * 8 + gid;
                bf[in][0] = __float_as_uint(Bst[(k0 + tig) * PB_ROW + ncol]);
                bf[in][1] = __float_as_uint(Bst[(k0 + tig + 4) * PB_ROW + ncol]);
            }
#pragma unroll
            for (int im = 0; im < 2; im++)
#pragma unroll
                for (int in = 0; in < 4; in++)
                    mma_tf32(acc[im][in], af[im], bf[in]);
        }
        __syncthreads();
    }

#pragma unroll
    for (int im = 0; im < 2; im++) {
#pragma unroll
        for (int in = 0; in < 4; in++) {
            int row = m0 + m_base + im * 16 + gid;
            int col = n0 + n_base + in * 8 + 2 * tig;
            if (row < M)
                *(float2*)(C + (size_t)row * N + col) = make_float2(acc[im][in][0], acc[im][in][1]);
            if (row + 8 < M)
                *(float2*)(C + (size_t)(row + 8) * N + col) = make_float2(acc[im][in][2], acc[im][in][3]);
        }
    }
}

// ---------------- dual SGEMM 64x64 FFMA (layer-3, N=32 each) ----------------
__global__ void __launch_bounds__(256, 4)
k_gemm_dual(const float* __restrict__ A,
            const float* __restrict__ B0, const float* __restrict__ B1,
            float* __restrict__ C0, float* __restrict__ C1,
            int M, int N, int K) {
    const float* B = blockIdx.z ? B1 : B0;
    float*       C = blockIdx.z ? C1 : C0;

    __shared__ __align__(16) float As[16][64];
    __shared__ __align__(16) float Bs[16][64];
    int tid = threadIdx.x;
    int tx = tid & 15, ty = tid >> 4;
    int m0 = blockIdx.y * 64, n0 = blockIdx.x * 64;

    float acc[4][4];
#pragma unroll
    for (int i = 0; i < 4; i++)
#pragma unroll
        for (int j = 0; j < 4; j++) acc[i][j] = 0.0f;

    for (int k0 = 0; k0 < K; k0 += 16) {
        {
            int r = tid >> 2;
            int kq = (tid & 3) * 4;
            int gm = m0 + r;
            float4 v = make_float4(0.f, 0.f, 0.f, 0.f);
            if (gm < M) v = *(const float4*)(A + (size_t)gm * K + k0 + kq);
            As[kq + 0][r] = v.x;
            As[kq + 1][r] = v.y;
            As[kq + 2][r] = v.z;
            As[kq + 3][r] = v.w;
        }
        {
            int r = tid >> 4;
            int cq = (tid & 15) * 4;
            int gn = n0 + cq;
            float4 v = make_float4(0.f, 0.f, 0.f, 0.f);
            if (gn + 3 < N) v = *(const float4*)(B + (size_t)(k0 + r) * N + gn);
            *(float4*)&Bs[r][cq] = v;
        }
        __syncthreads();
#pragma unroll
        for (int k = 0; k < 16; k++) {
            float4 a = *(const float4*)&As[k][ty * 4];
            float4 b = *(const float4*)&Bs[k][tx * 4];
            float ar[4] = {a.x, a.y, a.z, a.w};
            float br[4] = {b.x, b.y, b.z, b.w};
#pragma unroll
            for (int i = 0; i < 4; i++)
#pragma unroll
                for (int j = 0; j < 4; j++) acc[i][j] += ar[i] * br[j];
        }
        __syncthreads();
    }
#pragma unroll
    for (int i = 0; i < 4; i++) {
        int gm = m0 + ty * 4 + i;
        if (gm >= M) continue;
#pragma unroll
        for (int j = 0; j < 4; j++) {
            int gn = n0 + tx * 4 + j;
            if (gn < N) C[(size_t)gm * N + gn] = acc[i][j];
        }
    }
}

// ---------------- fused GAT edge phase: warp/node, quad online softmax ------
template <int H, int MODE>
__global__ void __launch_bounds__(256)
k_gat(const float* __restrict__ xl, const float* __restrict__ xr,
      const float* __restrict__ att, const float* __restrict__ bias,
      const int* __restrict__ row_ptr, const int* __restrict__ csr_src,
      const float* __restrict__ hres_in,
      float* __restrict__ out, float* __restrict__ hres_out) {
    constexpr int D = H * 32;
    constexpr int R = D / 32;
    constexpr int L = 32 / H;

    int node = (int)((blockIdx.x * (unsigned)blockDim.x + threadIdx.x) >> 5);
    int lane = threadIdx.x & 31;
    if (node >= NN) return;

    float xrv[R], attv[R], acc[R];
    {
        const float* xrp = xr + (size_t)node * D + lane * R;
#pragma unroll
        for (int q = 0; q < R / 4; q++) *(float4*)&xrv[q * 4] = *(const float4*)(xrp + q * 4);
#pragma unroll
        for (int j = (R / 4) * 4; j < R; j++) xrv[j] = xrp[j];
#pragma unroll
        for (int j = 0; j < R; j++) { attv[j] = att[lane * R + j]; acc[j] = 0.0f; }
    }
    float m = -CUDART_INF_F, denom = 0.0f;

    auto load_x = [&](int s, float* dstf) {
        const float* xp = xl + (size_t)s * D + lane * R;
#pragma unroll
        for (int q = 0; q < R / 4; q++) *(float4*)&dstf[q * 4] = *(const float4*)(xp + q * 4);
#pragma unroll
        for (int j = (R / 4) * 4; j < R; j++) dstf[j] = xp[j];
    };
    auto score = [&](const float* c) {
        float p = 0.0f;
#pragma unroll
        for (int j = 0; j < R; j++) {
            float v = c[j] + xrv[j];
            v = v > 0.0f ? v : 0.2f * v;
            p = fmaf(v, attv[j], p);
        }
        return p;
    };

    int e   = row_ptr[node];
    int end = row_ptr[node + 1];

    for (; e + 4 <= end; e += 4) {
        int s0 = csr_src[e], s1 = csr_src[e + 1], s2 = csr_src[e + 2], s3 = csr_src[e + 3];
        float c0[R], c1[R], c2[R], c3[R];
        load_x(s0, c0); load_x(s1, c1); load_x(s2, c2); load_x(s3, c3);

        float p0 = score(c0), p1 = score(c1), p2 = score(c2), p3 = score(c3);
#pragma unroll
        for (int o = 1; o < L; o <<= 1) {
            p0 += __shfl_xor_sync(0xffffffffu, p0, o);
            p1 += __shfl_xor_sync(0xffffffffu, p1, o);
            p2 += __shfl_xor_sync(0xffffffffu, p2, o);
            p3 += __shfl_xor_sync(0xffffffffu, p3, o);
        }

        float mq = fmaxf(fmaxf(p0, p1), fmaxf(p2, p3));
        float w0 = __expf(p0 - mq), w1 = __expf(p1 - mq);
        float w2 = __expf(p2 - mq), w3 = __expf(p3 - mq);
        float nm = fmaxf(m, mq);
        float so = __expf(m - nm);
        float sn = __expf(mq - nm);
        denom = denom * so + (w0 + w1 + w2 + w3) * sn;
        float w0n = w0 * sn, w1n = w1 * sn, w2n = w2 * sn, w3n = w3 * sn;
#pragma unroll
        for (int j = 0; j < R; j++) {
            float t = fmaf(w1n, c1[j], w0n * c0[j]);
            t = fmaf(w2n, c2[j], t);
            t = fmaf(w3n, c3[j], t);
            acc[j] = fmaf(acc[j], so, t);
        }
        m = nm;
    }
    for (; e + 2 <= end; e += 2) {
        int s0 = csr_src[e], s1 = csr_src[e + 1];
        float c0[R], c1[R];
        load_x(s0, c0); load_x(s1, c1);
        float p0 = score(c0), p1 = score(c1);
#pragma unroll
        for (int o = 1; o < L; o <<= 1) {
            p0 += __shfl_xor_sync(0xffffffffu, p0, o);
            p1 += __shfl_xor_sync(0xffffffffu, p1, o);
        }
        float mq = fmaxf(p0, p1);
        float w0 = __expf(p0 - mq), w1 = __expf(p1 - mq);
        float nm = fmaxf(m, mq);
        float so = __expf(m - nm);
        float sn = __expf(mq - nm);
        denom = denom * so + (w0 + w1) * sn;
        float w0n = w0 * sn, w1n = w1 * sn;
#pragma unroll
        for (int j = 0; j < R; j++) {
            float t = fmaf(w1n, c1[j], w0n * c0[j]);
            acc[j] = fmaf(acc[j], so, t);
        }
        m = nm;
    }
    if (e < end) {
        int s0 = csr_src[e];
        float c0[R];
        load_x(s0, c0);
        float p0 = score(c0);
#pragma unroll
        for (int o = 1; o < L; o <<= 1) p0 += __shfl_xor_sync(0xffffffffu, p0, o);
        float nm = fmaxf(m, p0);
        float so = __expf(m - nm);
        float w  = __expf(p0 - nm);
        denom = denom * so + w;
#pragma unroll
        for (int j = 0; j < R; j++) acc[j] = fmaf(acc[j], so, w * c0[j]);
        m = nm;
    }

    float inv = 1.0f / (denom + 1e-16f);
    float* op = out + (size_t)node * D + lane * R;
    float res[R];
#pragma unroll
    for (int j = 0; j < R; j++) {
        float v = acc[j] * inv + bias[lane * R + j];
        if (MODE == 0) v = v > 0.0f ? v : 0.0f;
        if (MODE == 1) v += hres_in[(size_t)node * D + lane * R + j];
        res[j] = v;
    }
    if (MODE == 0) {
        float* hp = hres_out + (size_t)node * D + lane * R;
        float rr[R];
#pragma unroll
        for (int j = 0; j < R; j++) rr[j] = rna(res[j]);
#pragma unroll
        for (int q = 0; q < R / 4; q++) {
            *(float4*)(hp + q * 4) = *(float4*)&res[q * 4];
            *(float4*)(op + q * 4) = *(float4*)&rr[q * 4];
        }
#pragma unroll
        for (int j = (R / 4) * 4; j < R; j++) { hp[j] = res[j]; op[j] = rr[j]; }
    } else {
#pragma unroll
        for (int q = 0; q < R / 4; q++) *(float4*)(op + q * 4) = *(float4*)&res[q * 4];
#pragma unroll
        for (int j = (R / 4) * 4; j < R; j++) op[j] = res[j];
    }
}

// ---------------- stream/event resources (host-side only) -------------------
struct SideStream {
    cudaStream_t s2;
    cudaEvent_t evFork, evJ1;
    SideStream() {
        cudaStreamCreateWithFlags(&s2, cudaStreamNonBlocking);
        cudaEventCreateWithFlags(&evFork, cudaEventDisableTiming);
        cudaEventCreateWithFlags(&evJ1, cudaEventDisableTiming);
    }
};

// ---------------- launch ----------------------------------------------------
extern "C" void kernel_launch(void* const* d_in, const int* in_sizes, int n_in,
                              void* d_out, int out_size) {
    const float* x   = (const float*)d_in[0];
    const float* W1l = (const float*)d_in[1];
    const float* W1r = (const float*)d_in[2];
    const float* a1  = (const float*)d_in[3];
    const float* b1  = (const float*)d_in[4];
    const float* W2l = (const float*)d_in[5];
    const float* W2r = (const float*)d_in[6];
    const float* a2  = (const float*)d_in[7];
    const float* b2  = (const float*)d_in[8];
    const float* W3l = (const float*)d_in[9];
    const float* W3r = (const float*)d_in[10];
    const float* a3  = (const float*)d_in[11];
    const float* b3  = (const float*)d_in[12];
    const void*  ei  = (const void*)d_in[13];
    float* out = (float*)d_out;

    float *xl, *xr, *hh, *hres, *w1l, *w1r, *w2l, *w2r;
    int *src, *dst, *csr, *rowp, *cur, *deg;
    cudaGetSymbolAddress((void**)&xl, g_xl);
    cudaGetSymbolAddress((void**)&xr, g_xr);
    cudaGetSymbolAddress((void**)&hh, g_h);
    cudaGetSymbolAddress((void**)&hres, g_hres);
    cudaGetSymbolAddress((void**)&w1l, g_w1l);
    cudaGetSymbolAddress((void**)&w1r, g_w1r);
    cudaGetSymbolAddress((void**)&w2l, g_w2l);
    cudaGetSymbolAddress((void**)&w2r, g_w2r);
    cudaGetSymbolAddress((void**)&src, g_src);
    cudaGetSymbolAddress((void**)&dst, g_dst);
    cudaGetSymbolAddress((void**)&csr, g_csr_src);
    cudaGetSymbolAddress((void**)&rowp, g_rowptr);
    cudaGetSymbolAddress((void**)&cur, g_cursor);
    cudaGetSymbolAddress((void**)&deg, g_deg);

    static SideStream S;

    const int TB = 256;
    int eb4 = (ET / 4 + TB - 1) / TB;
    int nwb = (NN * 32 + TB - 1) / TB;

    dim3 gBig((256 + 63) / 64, (NN + 127) / 128, 2);
    dim3 gSm(1, (NN + 63) / 64, 2);
    dim3 gRound((NN * 128 / 4 + TB - 1) / TB, 5);

    // fork the side stream INTO the capture (event on stream 0 first).
    cudaEventRecord(S.evFork, 0);
    cudaStreamWaitEvent(S.s2, S.evFork, 0);

    // main: CSR chain. side: round + GEMM1 (4th submission = ncu control slot).
    k_edges<<<eb4, TB>>>(ei, src, dst, deg);                                       // 1
    k_scan<<<1, 1024>>>(deg, rowp, cur);                                           // 2
    k_round5<<<gRound, TB, 0, S.s2>>>(x, hh, NN * 128,                             // 3
                                      W1l, w1l, 128 * 256,
                                      W1r, w1r, 128 * 256,
                                      W2l, w2l, 256 * 256,
                                      W2r, w2r, 256 * 256);
    k_gemm_tf32_dual<<<gBig, TB, 0, S.s2>>>(hh, w1l, w1r, xl, xr, NN, 256, 128);   // 4
    k_scatter<<<eb4, TB>>>(src, dst, cur, csr);                                    // 5
    cudaEventRecord(S.evJ1, S.s2);
    cudaStreamWaitEvent(0, S.evJ1, 0);

    // ---------- layer 1 (Fin=128, H=8) ----------
    k_gat<8, 0><<<nwb, TB>>>(xl, xr, a1, b1, rowp, csr, nullptr, hh, hres);

    // ---------- layer 2 (Fin=256, H=8, residual); hh is pre-rounded ----------
    k_gemm_tf32_dual<<<gBig, TB>>>(hh, w2l, w2r, xl, xr, NN, 256, 256);
    k_gat<8, 1><<<nwb, TB>>>(xl, xr, a2, b2, rowp, csr, hres, hh, nullptr);

    // ---------- layer 3 (Fin=256, H=1, FFMA fp32) ----------
    k_gemm_dual<<<gSm, TB>>>(hh, W3l, W3r, xl, xr, NN, 32, 256);
    k_gat<1, 2><<<nwb, TB>>>(xl, xr, a3, b3, rowp, csr, nullptr, out, nullptr);
}